// round 2
// baseline (speedup 1.0000x reference)
#include <cuda_runtime.h>

// VectorNet fused kernel for GB300 (sm_103a)
// B=32, NPOLY=256, VPP=64, L=32, PLEN=256
//
// Kernel A: one block per (b, poly). Runs 3 layers of GEMM+LN+ReLU+max-agg
//           using the agg-fold trick (concat half handled as a shared row term).
//           Emits agg2 (128 floats) per block to g_agg.
// Kernel B: one block per batch. Collapsed attention:
//           q = P_agent @ Wq' + bq;  t = Wk' q;  scores = P@t / 16; softmax;
//           out = (att@P) @ Wv' + bv.   (Wx' = Wx[:128]+Wx[128:], P = agg2)

#define NB 32
#define NPOLY_ 256

__device__ float g_agg[NB * NPOLY_ * 128];  // 4 MB scratch

// -------------------------------------------------------------------------
// GEMM (64 x OUT_C) = x(64 x K) @ W(K x OUT_C) + sterm, then LayerNorm+ReLU
// Thread tile: R rows x 8 cols.  Exactly 256 threads active for all layers:
//   layer0: K=32, OUT_C=32,  R=1  (64 rowgroups x 4 colgroups)
//   layer1: K=32, OUT_C=64,  R=2  (32 x 8)
//   layer2: K=64, OUT_C=128, R=4  (16 x 16)
// -------------------------------------------------------------------------
template <int K, int OUT_C, int R>
__device__ __forceinline__ void gemm_ln_relu(
    const float* __restrict__ xs, int xLD,
    float* __restrict__ hs, int hLD,
    const float* __restrict__ Ws,
    const float* __restrict__ gs, const float* __restrict__ bes,
    const float* __restrict__ sterm, int tid)
{
    constexpr int NCG = OUT_C / 8;
    const int rg = tid / NCG;
    const int cg = tid - rg * NCG;
    const int r0 = rg * R;
    const int c0 = cg * 8;

    float acc[R][8];
#pragma unroll
    for (int i = 0; i < R; i++)
#pragma unroll
        for (int j = 0; j < 8; j++) acc[i][j] = sterm[c0 + j];

#pragma unroll 8
    for (int k = 0; k < K; k++) {
        float4 wa = *reinterpret_cast<const float4*>(Ws + k * OUT_C + c0);
        float4 wb = *reinterpret_cast<const float4*>(Ws + k * OUT_C + c0 + 4);
#pragma unroll
        for (int i = 0; i < R; i++) {
            float xv = xs[(r0 + i) * xLD + k];
            acc[i][0] = fmaf(xv, wa.x, acc[i][0]);
            acc[i][1] = fmaf(xv, wa.y, acc[i][1]);
            acc[i][2] = fmaf(xv, wa.z, acc[i][2]);
            acc[i][3] = fmaf(xv, wa.w, acc[i][3]);
            acc[i][4] = fmaf(xv, wb.x, acc[i][4]);
            acc[i][5] = fmaf(xv, wb.y, acc[i][5]);
            acc[i][6] = fmaf(xv, wb.z, acc[i][6]);
            acc[i][7] = fmaf(xv, wb.w, acc[i][7]);
        }
    }

    const float invC = 1.0f / (float)OUT_C;
#pragma unroll
    for (int i = 0; i < R; i++) {
        float s = 0.f, s2 = 0.f;
#pragma unroll
        for (int j = 0; j < 8; j++) {
            s += acc[i][j];
            s2 = fmaf(acc[i][j], acc[i][j], s2);
        }
#pragma unroll
        for (int o = NCG / 2; o > 0; o >>= 1) {
            s  += __shfl_xor_sync(0xffffffffu, s, o);
            s2 += __shfl_xor_sync(0xffffffffu, s2, o);
        }
        float mu   = s * invC;
        float var  = fmaf(-mu, mu, s2 * invC);
        float rstd = rsqrtf(var + 1e-5f);
#pragma unroll
        for (int j = 0; j < 8; j++) {
            float v = fmaf((acc[i][j] - mu) * rstd, gs[c0 + j], bes[c0 + j]);
            hs[(r0 + i) * hLD + c0 + j] = fmaxf(v, 0.f);
        }
    }
}

// -------------------------------------------------------------------------
__global__ void __launch_bounds__(256, 1)
vn_main_kernel(const float* __restrict__ data,
               const float* __restrict__ W0g, const float* __restrict__ b0g,
               const float* __restrict__ g0g, const float* __restrict__ be0g,
               const float* __restrict__ W1g, const float* __restrict__ b1g,
               const float* __restrict__ g1g, const float* __restrict__ be1g,
               const float* __restrict__ W2g, const float* __restrict__ b2g,
               const float* __restrict__ g2g, const float* __restrict__ be2g)
{
    extern __shared__ float sm[];
    float* W0   = sm;                  // 1024
    float* W1   = W0 + 1024;           // 4096
    float* W2   = W1 + 4096;           // 16384
    float* g0   = W2 + 16384;  float* be0 = g0 + 32;
    float* g1   = be0 + 32;    float* be1 = g1 + 64;
    float* g2   = be1 + 64;    float* be2 = g2 + 128;
    float* bufA = be2 + 128;           // 64*65  = 4160 (x0 @LD33, h1 @LD65)
    float* bufB = bufA + 4160;         // 64*129 = 8256 (h0 @LD33, h2 @LD129)
    float* agg  = bufB + 8256;         // 128
    float* sterm = agg + 128;          // 128

    const int tid = threadIdx.x;
    const int p = blockIdx.x, b = blockIdx.y;

    // stage weights + LN params into smem (L2-hot after wave 1)
    for (int i = tid; i < 256;  i += 256) ((float4*)W0)[i] = ((const float4*)W0g)[i];
    for (int i = tid; i < 1024; i += 256) ((float4*)W1)[i] = ((const float4*)W1g)[i];
    for (int i = tid; i < 4096; i += 256) ((float4*)W2)[i] = ((const float4*)W2g)[i];
    if (tid < 32)  { g0[tid] = g0g[tid]; be0[tid] = be0g[tid]; }
    if (tid < 64)  { g1[tid] = g1g[tid]; be1[tid] = be1g[tid]; }
    if (tid < 128) { g2[tid] = g2g[tid]; be2[tid] = be2g[tid]; }

    // x0: 64 rows x 32 ch, last channel zeroed (pid column)
    const float* base = data + ((size_t)b * 16385 + 1 + (size_t)p * 64) * 32;
    for (int e = tid; e < 2048; e += 256) {
        int r = e >> 5, k = e & 31;
        float v = base[e];
        bufA[r * 33 + k] = (k == 31) ? 0.f : v;
    }
    if (tid < 32) sterm[tid] = b0g[tid];
    __syncthreads();

    // ---- layer 0 ----
    gemm_ln_relu<32, 32, 1>(bufA, 33, bufB, 33, W0, g0, be0, sterm, tid);
    __syncthreads();
    if (tid < 32) {
        float m = 0.f;
        for (int r = 0; r < 64; r++) m = fmaxf(m, bufB[r * 33 + tid]);
        agg[tid] = m;
    }
    __syncthreads();

    // ---- layer 1 ----  sterm = b1 + agg0 @ W1[32:64]
    if (tid < 64) {
        float v = b1g[tid];
        for (int k = 0; k < 32; k++) v = fmaf(agg[k], W1[(32 + k) * 64 + tid], v);
        sterm[tid] = v;
    }
    __syncthreads();
    gemm_ln_relu<32, 64, 2>(bufB, 33, bufA, 65, W1, g1, be1, sterm, tid);
    __syncthreads();
    if (tid < 64) {
        float m = 0.f;
        for (int r = 0; r < 64; r++) m = fmaxf(m, bufA[r * 65 + tid]);
        agg[tid] = m;
    }
    __syncthreads();

    // ---- layer 2 ----  sterm = b2 + agg1 @ W2[64:128]
    if (tid < 128) {
        float v = b2g[tid];
        for (int k = 0; k < 64; k++) v = fmaf(agg[k], W2[(64 + k) * 128 + tid], v);
        sterm[tid] = v;
    }
    __syncthreads();
    gemm_ln_relu<64, 128, 4>(bufA, 65, bufB, 129, W2, g2, be2, sterm, tid);
    __syncthreads();

    // agg2 == P[b,p,:128] == P[b,p,128:256]; emit it
    if (tid < 128) {
        float m = 0.f;
        for (int r = 0; r < 64; r++) m = fmaxf(m, bufB[r * 129 + tid]);
        g_agg[((size_t)(b * 256 + p)) * 128 + tid] = m;
    }
}

// -------------------------------------------------------------------------
__global__ void __launch_bounds__(256, 1)
vn_attn_kernel(const float* __restrict__ data,
               const float* __restrict__ Wq, const float* __restrict__ bq,
               const float* __restrict__ Wk,
               const float* __restrict__ Wv, const float* __restrict__ bv,
               float* __restrict__ out)
{
    extern __shared__ float sm[];
    float* Pb   = sm;            // 256*129 = 33024 (padded vs bank conflicts)
    float* q    = Pb + 33024;    // 256
    float* t    = q + 256;       // 128
    float* sc   = t + 128;       // 256
    float* w128 = sc + 256;      // 128
    float* red  = w128 + 128;    // 32

    const int tid = threadIdx.x, lane = tid & 31, w = tid >> 5;
    const int b = blockIdx.x;

    const float* P = g_agg + (size_t)b * 256 * 128;
    for (int e = tid; e < 32768; e += 256) {
        int p = e >> 7, j = e & 127;
        Pb[p * 129 + j] = P[e];
    }
    if (tid == 0) red[0] = data[(size_t)b * 16385 * 32];  // agent id (data[b,0,0])
    __syncthreads();
    const int aid = (int)red[0];

    // q = P[agent] @ Wq' + bq   (Wq' = Wq[:128]+Wq[128:])
    {
        float s = bq[tid];
        const float* pr = Pb + aid * 129;
        for (int j = 0; j < 128; j++)
            s = fmaf(pr[j], Wq[j * 256 + tid] + Wq[(j + 128) * 256 + tid], s);
        q[tid] = s;
    }
    __syncthreads();

    // t = Wk' @ q  (warp-per-row, coalesced)
    for (int jj = 0; jj < 16; jj++) {
        int j = w * 16 + jj;
        float a = 0.f;
#pragma unroll
        for (int m = 0; m < 8; m++) {
            int c = lane + m * 32;
            a = fmaf(Wk[j * 256 + c] + Wk[(j + 128) * 256 + c], q[c], a);
        }
#pragma unroll
        for (int o = 16; o > 0; o >>= 1) a += __shfl_xor_sync(0xffffffffu, a, o);
        if (lane == 0) t[j] = a;
    }
    __syncthreads();

    // scores[p] = (P[p] . t) / sqrt(256)   (q.bk shift is softmax-invariant)
    for (int pp = 0; pp < 32; pp++) {
        int p = w * 32 + pp;
        float a = 0.f;
#pragma unroll
        for (int m = 0; m < 4; m++) {
            int j = lane + m * 32;
            a = fmaf(Pb[p * 129 + j], t[j], a);
        }
#pragma unroll
        for (int o = 16; o > 0; o >>= 1) a += __shfl_xor_sync(0xffffffffu, a, o);
        if (lane == 0) sc[p] = a * 0.0625f;
    }
    __syncthreads();

    // softmax over 256
    float v = sc[tid];
    float mx = v;
#pragma unroll
    for (int o = 16; o > 0; o >>= 1) mx = fmaxf(mx, __shfl_xor_sync(0xffffffffu, mx, o));
    if (lane == 0) red[w] = mx;
    __syncthreads();
    if (tid == 0) {
        float M = red[0];
        for (int i = 1; i < 8; i++) M = fmaxf(M, red[i]);
        red[8] = M;
    }
    __syncthreads();
    float e = __expf(v - red[8]);
    float se = e;
#pragma unroll
    for (int o = 16; o > 0; o >>= 1) se += __shfl_xor_sync(0xffffffffu, se, o);
    if (lane == 0) red[16 + w] = se;
    __syncthreads();
    if (tid == 0) {
        float S = 0.f;
        for (int i = 0; i < 8; i++) S += red[16 + i];
        red[24] = 1.f / S;
    }
    __syncthreads();
    sc[tid] = e * red[24];  // att
    __syncthreads();

    // w128 = att @ P
    if (tid < 128) {
        float a = 0.f;
        for (int p = 0; p < 256; p++) a = fmaf(sc[p], Pb[p * 129 + tid], a);
        w128[tid] = a;
    }
    __syncthreads();

    // out = w128 @ Wv' + bv
    {
        float o = bv[tid];
        for (int j = 0; j < 128; j++)
            o = fmaf(w128[j], Wv[j * 256 + tid] + Wv[(j + 128) * 256 + tid], o);
        out[b * 256 + tid] = o;
    }
}

// -------------------------------------------------------------------------
extern "C" void kernel_launch(void* const* d_in, const int* in_sizes, int n_in,
                              void* d_out, int out_size)
{
    const float* data = (const float*)d_in[0];
    const float* W0  = (const float*)d_in[1];
    const float* b0  = (const float*)d_in[2];
    const float* g0  = (const float*)d_in[3];
    const float* be0 = (const float*)d_in[4];
    const float* W1  = (const float*)d_in[5];
    const float* b1  = (const float*)d_in[6];
    const float* g1  = (const float*)d_in[7];
    const float* be1 = (const float*)d_in[8];
    const float* W2  = (const float*)d_in[9];
    const float* b2  = (const float*)d_in[10];
    const float* g2  = (const float*)d_in[11];
    const float* be2 = (const float*)d_in[12];
    const float* Wq  = (const float*)d_in[13];
    const float* bq  = (const float*)d_in[14];
    const float* Wk  = (const float*)d_in[15];
    // d_in[16] = bk: softmax-invariant shift, provably unused
    const float* Wv  = (const float*)d_in[17];
    const float* bv  = (const float*)d_in[18];
    float* out = (float*)d_out;

    const size_t smA = (size_t)(1024 + 4096 + 16384 + 448 + 4160 + 8256 + 128 + 128) * sizeof(float);
    const size_t smB = (size_t)(33024 + 256 + 128 + 256 + 128 + 32) * sizeof(float);
    cudaFuncSetAttribute(vn_main_kernel, cudaFuncAttributeMaxDynamicSharedMemorySize, (int)smA);
    cudaFuncSetAttribute(vn_attn_kernel, cudaFuncAttributeMaxDynamicSharedMemorySize, (int)smB);

    dim3 gridA(NPOLY_, NB);
    vn_main_kernel<<<gridA, 256, smA>>>(data, W0, b0, g0, be0,
                                        W1, b1, g1, be1, W2, b2, g2, be2);
    vn_attn_kernel<<<NB, 256, smB>>>(data, Wq, bq, Wk, Wv, bv, out);
}

// round 6
// speedup vs baseline: 1.4867x; 1.4867x over previous
#include <cuda_runtime.h>

// VectorNet fused, round 2: persistent main kernel, 2 polys/block, 512 thr.
// B=32, NPOLY=256, VPP=64, L=32, PLEN=256

#define NB 32
#define NPOLY_ 256
#define NPAIRS 4096   // 32 batches * 128 poly-pairs
#define MAIN_GRID 148

__device__ float g_agg[NB * NPOLY_ * 128];  // 4 MB scratch

// ---------------------------------------------------------------------------
// GEMM (64 x OUT_C) = x(64 x K) @ W(K x OUT_C) + sterm, then LayerNorm+ReLU.
// 256 threads per poly. Thread tile R rows x 8 cols. k chunked by 4 w/ float4.
// ---------------------------------------------------------------------------
template <int K, int OUT_C, int R, int XLD, int HLD>
__device__ __forceinline__ void gemm_ln_relu(
    const float* __restrict__ xs, float* __restrict__ hs,
    const float* __restrict__ Ws, const float* __restrict__ gs,
    const float* __restrict__ bes, const float* __restrict__ sterm, int ltid)
{
    constexpr int NCG = OUT_C / 8;
    const int rg = ltid / NCG, cg = ltid % NCG;
    const int r0 = rg * R, c0 = cg * 8;

    float acc[R][8];
#pragma unroll
    for (int i = 0; i < R; i++)
#pragma unroll
        for (int j = 0; j < 8; j++) acc[i][j] = sterm[c0 + j];

#pragma unroll
    for (int k0 = 0; k0 < K; k0 += 4) {
        float xv[R][4];
#pragma unroll
        for (int i = 0; i < R; i++) {
            float4 t = *reinterpret_cast<const float4*>(xs + (r0 + i) * XLD + k0);
            xv[i][0] = t.x; xv[i][1] = t.y; xv[i][2] = t.z; xv[i][3] = t.w;
        }
#pragma unroll
        for (int kk = 0; kk < 4; kk++) {
            float4 wa = *reinterpret_cast<const float4*>(Ws + (k0 + kk) * OUT_C + c0);
            float4 wb = *reinterpret_cast<const float4*>(Ws + (k0 + kk) * OUT_C + c0 + 4);
#pragma unroll
            for (int i = 0; i < R; i++) {
                float x = xv[i][kk];
                acc[i][0] = fmaf(x, wa.x, acc[i][0]);
                acc[i][1] = fmaf(x, wa.y, acc[i][1]);
                acc[i][2] = fmaf(x, wa.z, acc[i][2]);
                acc[i][3] = fmaf(x, wa.w, acc[i][3]);
                acc[i][4] = fmaf(x, wb.x, acc[i][4]);
                acc[i][5] = fmaf(x, wb.y, acc[i][5]);
                acc[i][6] = fmaf(x, wb.z, acc[i][6]);
                acc[i][7] = fmaf(x, wb.w, acc[i][7]);
            }
        }
    }

    const float invC = 1.0f / (float)OUT_C;
#pragma unroll
    for (int i = 0; i < R; i++) {
        float s = 0.f, s2 = 0.f;
#pragma unroll
        for (int j = 0; j < 8; j++) {
            s += acc[i][j];
            s2 = fmaf(acc[i][j], acc[i][j], s2);
        }
#pragma unroll
        for (int o = NCG / 2; o > 0; o >>= 1) {
            s  += __shfl_xor_sync(0xffffffffu, s, o);
            s2 += __shfl_xor_sync(0xffffffffu, s2, o);
        }
        float mu   = s * invC;
        float var  = fmaf(-mu, mu, s2 * invC);
        float rstd = rsqrtf(var + 1e-5f);
        float4 o1, o2;
        o1.x = fmaxf(fmaf((acc[i][0] - mu) * rstd, gs[c0 + 0], bes[c0 + 0]), 0.f);
        o1.y = fmaxf(fmaf((acc[i][1] - mu) * rstd, gs[c0 + 1], bes[c0 + 1]), 0.f);
        o1.z = fmaxf(fmaf((acc[i][2] - mu) * rstd, gs[c0 + 2], bes[c0 + 2]), 0.f);
        o1.w = fmaxf(fmaf((acc[i][3] - mu) * rstd, gs[c0 + 3], bes[c0 + 3]), 0.f);
        o2.x = fmaxf(fmaf((acc[i][4] - mu) * rstd, gs[c0 + 4], bes[c0 + 4]), 0.f);
        o2.y = fmaxf(fmaf((acc[i][5] - mu) * rstd, gs[c0 + 5], bes[c0 + 5]), 0.f);
        o2.z = fmaxf(fmaf((acc[i][6] - mu) * rstd, gs[c0 + 6], bes[c0 + 6]), 0.f);
        o2.w = fmaxf(fmaf((acc[i][7] - mu) * rstd, gs[c0 + 7], bes[c0 + 7]), 0.f);
        *reinterpret_cast<float4*>(hs + (r0 + i) * HLD + c0)     = o1;
        *reinterpret_cast<float4*>(hs + (r0 + i) * HLD + c0 + 4) = o2;
    }
}

// Parallel column-max over 64 rows (post-ReLU, values >= 0).
template <int NC, int LD>
__device__ __forceinline__ void colmax(const float* __restrict__ hs,
                                       float* __restrict__ part,
                                       float* __restrict__ agg, int ltid)
{
    constexpr int NCH = 256 / NC;
    constexpr int RP  = 64 / NCH;
    const int col = ltid % NC, ch = ltid / NC;
    float m = 0.f;
#pragma unroll
    for (int r = 0; r < RP; r++) m = fmaxf(m, hs[(ch * RP + r) * LD + col]);
    part[ch * NC + col] = m;
    __syncthreads();
    if (ltid < NC) {
        float mm = part[col];
#pragma unroll
        for (int c = 1; c < NCH; c++) mm = fmaxf(mm, part[c * NC + col]);
        agg[col] = mm;
    }
}

// sterm = bias + agg @ Wlow  (Wlow row stride == NC), k split across segs.
template <int NC, int KA>
__device__ __forceinline__ void sterm_calc(const float* __restrict__ Wlow,
                                           const float* __restrict__ bg,
                                           const float* __restrict__ agg,
                                           float* __restrict__ part,
                                           float* __restrict__ sterm, int ltid)
{
    constexpr int NSEG = 256 / NC;
    constexpr int KS   = KA / NSEG;
    const int col = ltid % NC, seg = ltid / NC;
    float s = 0.f;
#pragma unroll
    for (int k = 0; k < KS; k++)
        s = fmaf(agg[seg * KS + k], Wlow[(seg * KS + k) * NC + col], s);
    part[seg * NC + col] = s;
    __syncthreads();
    if (ltid < NC) {
        float v = bg[col];
#pragma unroll
        for (int c = 0; c < NSEG; c++) v += part[c * NC + col];
        sterm[col] = v;
    }
}

// ---------------------------------------------------------------------------
// Persistent main kernel: grid=148, 512 threads, 2 polys per block per tile.
// ---------------------------------------------------------------------------
__global__ void __launch_bounds__(512, 1)
vn_main_kernel(const float* __restrict__ data,
               const float* __restrict__ W0g, const float* __restrict__ b0g,
               const float* __restrict__ g0g, const float* __restrict__ be0g,
               const float* __restrict__ W1g, const float* __restrict__ b1g,
               const float* __restrict__ g1g, const float* __restrict__ be1g,
               const float* __restrict__ W2g, const float* __restrict__ b2g,
               const float* __restrict__ g2g, const float* __restrict__ be2g)
{
    extern __shared__ float sm[];
    // shared weight area
    float* W0s  = sm;            // 1024
    float* W1s  = sm + 1024;     // 4096
    float* W2s  = sm + 5120;     // 16384
    float* g0s  = sm + 21504;  float* be0s = sm + 21536;
    float* g1s  = sm + 21568;  float* be1s = sm + 21632;
    float* g2s  = sm + 21696;  float* be2s = sm + 21824;
    float* b0s  = sm + 21952;  float* b1s  = sm + 21984;
    float* b2s  = sm + 22048;  // ends 22176

    const int tid  = threadIdx.x;
    const int hp   = tid >> 8;        // which poly of the pair
    const int ltid = tid & 255;

    float* pb    = sm + 22176 + hp * 13312;
    float* bufA  = pb;           // 4352 (x0 @LD36, h1 @LD68)
    float* bufB  = pb + 4352;    // 8448 (h0 @LD36, h2 @LD132)
    float* agg   = pb + 12800;   // 128
    float* sterm = pb + 12928;   // 128
    float* part  = pb + 13056;   // 256

    // stage weights once per block
    for (int i = tid; i < 256;  i += 512) ((float4*)W0s)[i] = ((const float4*)W0g)[i];
    for (int i = tid; i < 1024; i += 512) ((float4*)W1s)[i] = ((const float4*)W1g)[i];
    for (int i = tid; i < 4096; i += 512) ((float4*)W2s)[i] = ((const float4*)W2g)[i];
    if (tid < 32)  { g0s[tid] = g0g[tid]; be0s[tid] = be0g[tid]; b0s[tid] = b0g[tid]; }
    else if (tid < 96)  { g1s[tid-32] = g1g[tid-32]; be1s[tid-32] = be1g[tid-32]; b1s[tid-32] = b1g[tid-32]; }
    else if (tid < 224) { g2s[tid-96] = g2g[tid-96]; be2s[tid-96] = be2g[tid-96]; b2s[tid-96] = b2g[tid-96]; }

    for (int pair = blockIdx.x; pair < NPAIRS; pair += gridDim.x) {
        const int b    = pair >> 7;
        const int poly = ((pair & 127) << 1) + hp;

        __syncthreads();   // protect buffers from previous tile + weight staging

        // load x0 (64 x 32), zero channel 31
        const float* base = data + ((size_t)b * 16385 + 1 + (size_t)poly * 64) * 32;
        for (int e4 = ltid; e4 < 512; e4 += 256) {
            float4 v = ((const float4*)base)[e4];
            int r = e4 >> 3, kq = e4 & 7;
            if (kq == 7) v.w = 0.f;
            *reinterpret_cast<float4*>(bufA + r * 36 + kq * 4) = v;
        }
        __syncthreads();

        // layer 0
        gemm_ln_relu<32, 32, 1, 36, 36>(bufA, bufB, W0s, g0s, be0s, b0s, ltid);
        __syncthreads();
        colmax<32, 36>(bufB, part, agg, ltid);
        __syncthreads();

        // layer 1
        sterm_calc<64, 32>(W1s + 32 * 64, b1s, agg, part, sterm, ltid);
        __syncthreads();
        gemm_ln_relu<32, 64, 2, 36, 68>(bufB, bufA, W1s, g1s, be1s, sterm, ltid);
        __syncthreads();
        colmax<64, 68>(bufA, part, agg, ltid);
        __syncthreads();

        // layer 2
        sterm_calc<128, 64>(W2s + 64 * 128, b2s, agg, part, sterm, ltid);
        __syncthreads();
        gemm_ln_relu<64, 128, 4, 68, 132>(bufA, bufB, W2s, g2s, be2s, sterm, ltid);
        __syncthreads();
        colmax<128, 132>(bufB, part, agg, ltid);
        __syncthreads();

        if (ltid < 128)
            g_agg[((size_t)(b * 256 + poly)) * 128 + ltid] = agg[ltid];
    }
}

// ---------------------------------------------------------------------------
// Attention kernel: one block per batch, 512 threads, split partials.
// q = P[agent]@Wq'+bq; t = Wk'q; scores = P@t/16; softmax; out = (att@P)@Wv'+bv
// (Wx' = Wx[:128]+Wx[128:] since P halves are identical; bk drops in softmax)
// ---------------------------------------------------------------------------
__global__ void __launch_bounds__(512, 1)
vn_attn_kernel(const float* __restrict__ data,
               const float* __restrict__ Wq, const float* __restrict__ bq,
               const float* __restrict__ Wk,
               const float* __restrict__ Wv, const float* __restrict__ bv,
               float* __restrict__ out)
{
    extern __shared__ float sm[];
    float* Pb   = sm;            // 256*132 = 33792
    float* q    = Pb + 33792;    // 256
    float* t    = q + 256;       // 128
    float* sc   = t + 128;       // 256
    float* w128 = sc + 256;      // 128
    float* red  = w128 + 128;    // 32
    float* part = red + 32;      // 512

    const int tid = threadIdx.x, lane = tid & 31, w = tid >> 5;
    const int b = blockIdx.x;

    const float* P = g_agg + (size_t)b * 256 * 128;
    for (int e4 = tid; e4 < 8192; e4 += 512) {
        int p = e4 >> 5, j4 = e4 & 31;
        *reinterpret_cast<float4*>(Pb + p * 132 + j4 * 4) = ((const float4*)P)[e4];
    }
    if (tid == 0) red[0] = data[(size_t)b * 16385 * 32];  // agent id
    __syncthreads();
    const int aid = (int)red[0];

    // q = P[agent] @ Wq' + bq  (k-split 2-way)
    {
        const int col = tid & 255, half = tid >> 8;
        const float* pr = Pb + aid * 132;
        float s = 0.f;
        for (int j = half * 64; j < half * 64 + 64; j++)
            s = fmaf(pr[j], Wq[j * 256 + col] + Wq[(j + 128) * 256 + col], s);
        part[half * 256 + col] = s;
    }
    __syncthreads();
    if (tid < 256) q[tid] = bq[tid] + part[tid] + part[256 + tid];
    __syncthreads();

    // t = Wk' @ q  (16 warps x 8 rows)
    for (int jj = 0; jj < 8; jj++) {
        int j = w * 8 + jj;
        float a = 0.f;
#pragma unroll
        for (int m = 0; m < 8; m++) {
            int c = lane + m * 32;
            a = fmaf(Wk[j * 256 + c] + Wk[(j + 128) * 256 + c], q[c], a);
        }
#pragma unroll
        for (int o = 16; o > 0; o >>= 1) a += __shfl_xor_sync(0xffffffffu, a, o);
        if (lane == 0) t[j] = a;
    }
    __syncthreads();

    // scores[p] = (P[p].t)/16  (16 warps x 16 rows)
    for (int pp = 0; pp < 16; pp++) {
        int p = w * 16 + pp;
        float a = 0.f;
#pragma unroll
        for (int m = 0; m < 4; m++) {
            int j = lane + m * 32;
            a = fmaf(Pb[p * 132 + j], t[j], a);
        }
#pragma unroll
        for (int o = 16; o > 0; o >>= 1) a += __shfl_xor_sync(0xffffffffu, a, o);
        if (lane == 0) sc[p] = a * 0.0625f;
    }
    __syncthreads();

    // softmax over 256 (threads 0..255)
    float v = 0.f, e = 0.f;
    if (tid < 256) {
        v = sc[tid];
        float mx = v;
#pragma unroll
        for (int o = 16; o > 0; o >>= 1) mx = fmaxf(mx, __shfl_xor_sync(0xffffffffu, mx, o));
        if (lane == 0) red[w] = mx;
    }
    __syncthreads();
    if (tid == 0) {
        float M = red[0];
        for (int i = 1; i < 8; i++) M = fmaxf(M, red[i]);
        red[8] = M;
    }
    __syncthreads();
    if (tid < 256) {
        e = __expf(v - red[8]);
        float se = e;
#pragma unroll
        for (int o = 16; o > 0; o >>= 1) se += __shfl_xor_sync(0xffffffffu, se, o);
        if (lane == 0) red[16 + w] = se;
    }
    __syncthreads();
    if (tid == 0) {
        float S = 0.f;
        for (int i = 0; i < 8; i++) S += red[16 + i];
        red[24] = 1.f / S;
    }
    __syncthreads();
    if (tid < 256) sc[tid] = e * red[24];
    __syncthreads();

    // w128 = att @ P  (4-way row split)
    {
        const int col = tid & 127, seg = tid >> 7;
        float a = 0.f;
        for (int p = seg * 64; p < seg * 64 + 64; p++)
            a = fmaf(sc[p], Pb[p * 132 + col], a);
        part[seg * 128 + col] = a;
    }
    __syncthreads();
    if (tid < 128)
        w128[tid] = part[tid] + part[128 + tid] + part[256 + tid] + part[384 + tid];
    __syncthreads();

    // out = w128 @ Wv' + bv  (k-split 2-way)
    {
        const int col = tid & 255, half = tid >> 8;
        float o = 0.f;
        for (int j = half * 64; j < half * 64 + 64; j++)
            o = fmaf(w128[j], Wv[j * 256 + col] + Wv[(j + 128) * 256 + col], o);
        part[half * 256 + col] = o;
    }
    __syncthreads();
    if (tid < 256) out[b * 256 + tid] = bv[tid] + part[tid] + part[256 + tid];
}

// ---------------------------------------------------------------------------
extern "C" void kernel_launch(void* const* d_in, const int* in_sizes, int n_in,
                              void* d_out, int out_size)
{
    const float* data = (const float*)d_in[0];
    const float* W0  = (const float*)d_in[1];
    const float* b0  = (const float*)d_in[2];
    const float* g0  = (const float*)d_in[3];
    const float* be0 = (const float*)d_in[4];
    const float* W1  = (const float*)d_in[5];
    const float* b1  = (const float*)d_in[6];
    const float* g1  = (const float*)d_in[7];
    const float* be1 = (const float*)d_in[8];
    const float* W2  = (const float*)d_in[9];
    const float* b2  = (const float*)d_in[10];
    const float* g2  = (const float*)d_in[11];
    const float* be2 = (const float*)d_in[12];
    const float* Wq  = (const float*)d_in[13];
    const float* bq  = (const float*)d_in[14];
    const float* Wk  = (const float*)d_in[15];
    // d_in[16] = bk: softmax-invariant, unused
    const float* Wv  = (const float*)d_in[17];
    const float* bv  = (const float*)d_in[18];
    float* out = (float*)d_out;

    const size_t smA = (size_t)(22176 + 2 * 13312) * sizeof(float);  // ~190.6 KB
    const size_t smB = (size_t)(33792 + 256 + 128 + 256 + 128 + 32 + 512) * sizeof(float);
    cudaFuncSetAttribute(vn_main_kernel, cudaFuncAttributeMaxDynamicSharedMemorySize, (int)smA);
    cudaFuncSetAttribute(vn_attn_kernel, cudaFuncAttributeMaxDynamicSharedMemorySize, (int)smB);

    vn_main_kernel<<<MAIN_GRID, 512, smA>>>(data, W0, b0, g0, be0,
                                            W1, b1, g1, be1, W2, b2, g2, be2);
    vn_attn_kernel<<<NB, 512, smB>>>(data, Wq, bq, Wk, Wv, bv, out);
}

// round 9
// speedup vs baseline: 1.5657x; 1.0531x over previous
#include <cuda_runtime.h>

// VectorNet fused, round 6: 512-thread persistent blocks, two decoupled
// 256-thread halves (named barriers) sharing one smem weight copy.
// Layer-2 max fused into GEMM epilogue (h2 never stored). x0 reg-prefetch.
// B=32, NPOLY=256, VPP=64, L=32, PLEN=256

#define NB 32
#define NPOLY_ 256
#define NPAIRS 4096   // 32 batches * 128 poly-pairs
#define MAIN_GRID 148

__device__ float g_agg[NB * NPOLY_ * 128];  // 4 MB scratch

// half-local barrier: 256 threads, barrier id 1 or 2
__device__ __forceinline__ void hbar(int hp) {
    asm volatile("bar.sync %0, 256;" :: "r"(hp + 1) : "memory");
}

// ---------------------------------------------------------------------------
// GEMM (64 x OUT_C) = x(64 x K) @ W(K x OUT_C) + sterm, then LayerNorm+ReLU.
// 256 threads per half. Thread tile R rows x 8 cols.
// STORE=true : write h to hs (row stride HLD).
// STORE=false: never materialize h; per-thread row-max -> hs[rg*HLD + c].
// ---------------------------------------------------------------------------
template <int K, int OUT_C, int R, int XLD, int HLD, bool STORE>
__device__ __forceinline__ void gemm_ln_relu(
    const float* __restrict__ xs, float* __restrict__ hs,
    const float* __restrict__ Ws, const float* __restrict__ gs,
    const float* __restrict__ bes, const float* __restrict__ sterm, int ltid)
{
    constexpr int NCG = OUT_C / 8;
    const int rg = ltid / NCG, cg = ltid % NCG;
    const int r0 = rg * R, c0 = cg * 8;

    float acc[R][8];
#pragma unroll
    for (int i = 0; i < R; i++)
#pragma unroll
        for (int j = 0; j < 8; j++) acc[i][j] = sterm[c0 + j];

#pragma unroll 4
    for (int k0 = 0; k0 < K; k0 += 4) {
        float xv[R][4];
#pragma unroll
        for (int i = 0; i < R; i++) {
            float4 t = *reinterpret_cast<const float4*>(xs + (r0 + i) * XLD + k0);
            xv[i][0] = t.x; xv[i][1] = t.y; xv[i][2] = t.z; xv[i][3] = t.w;
        }
#pragma unroll
        for (int kk = 0; kk < 4; kk++) {
            float4 wa = *reinterpret_cast<const float4*>(Ws + (k0 + kk) * OUT_C + c0);
            float4 wb = *reinterpret_cast<const float4*>(Ws + (k0 + kk) * OUT_C + c0 + 4);
#pragma unroll
            for (int i = 0; i < R; i++) {
                float x = xv[i][kk];
                acc[i][0] = fmaf(x, wa.x, acc[i][0]);
                acc[i][1] = fmaf(x, wa.y, acc[i][1]);
                acc[i][2] = fmaf(x, wa.z, acc[i][2]);
                acc[i][3] = fmaf(x, wa.w, acc[i][3]);
                acc[i][4] = fmaf(x, wb.x, acc[i][4]);
                acc[i][5] = fmaf(x, wb.y, acc[i][5]);
                acc[i][6] = fmaf(x, wb.z, acc[i][6]);
                acc[i][7] = fmaf(x, wb.w, acc[i][7]);
            }
        }
    }

    const float invC = 1.0f / (float)OUT_C;
    float mx[8];
    if (!STORE) {
#pragma unroll
        for (int j = 0; j < 8; j++) mx[j] = 0.f;
    }

#pragma unroll
    for (int i = 0; i < R; i++) {
        float s = 0.f, s2 = 0.f;
#pragma unroll
        for (int j = 0; j < 8; j++) {
            s += acc[i][j];
            s2 = fmaf(acc[i][j], acc[i][j], s2);
        }
#pragma unroll
        for (int o = NCG / 2; o > 0; o >>= 1) {
            s  += __shfl_xor_sync(0xffffffffu, s, o);
            s2 += __shfl_xor_sync(0xffffffffu, s2, o);
        }
        float mu   = s * invC;
        float var  = fmaf(-mu, mu, s2 * invC);
        float rstd = rsqrtf(var + 1e-5f);
        float v[8];
#pragma unroll
        for (int j = 0; j < 8; j++)
            v[j] = fmaxf(fmaf((acc[i][j] - mu) * rstd, gs[c0 + j], bes[c0 + j]), 0.f);

        if (STORE) {
            float4 o1 = {v[0], v[1], v[2], v[3]};
            float4 o2 = {v[4], v[5], v[6], v[7]};
            *reinterpret_cast<float4*>(hs + (r0 + i) * HLD + c0)     = o1;
            *reinterpret_cast<float4*>(hs + (r0 + i) * HLD + c0 + 4) = o2;
        } else {
#pragma unroll
            for (int j = 0; j < 8; j++) mx[j] = fmaxf(mx[j], v[j]);
        }
    }

    if (!STORE) {
        float4 m1 = {mx[0], mx[1], mx[2], mx[3]};
        float4 m2 = {mx[4], mx[5], mx[6], mx[7]};
        *reinterpret_cast<float4*>(hs + rg * HLD + c0)     = m1;
        *reinterpret_cast<float4*>(hs + rg * HLD + c0 + 4) = m2;
    }
}

// Parallel column-max over 64 rows (post-ReLU, values >= 0).
template <int NC, int LD>
__device__ __forceinline__ void colmax(const float* __restrict__ hs,
                                       float* __restrict__ part,
                                       float* __restrict__ agg, int ltid, int hp)
{
    constexpr int NCH = 256 / NC;
    constexpr int RP  = 64 / NCH;
    const int col = ltid % NC, ch = ltid / NC;
    float m = 0.f;
#pragma unroll
    for (int r = 0; r < RP; r++) m = fmaxf(m, hs[(ch * RP + r) * LD + col]);
    part[ch * NC + col] = m;
    hbar(hp);
    if (ltid < NC) {
        float mm = part[col];
#pragma unroll
        for (int c = 1; c < NCH; c++) mm = fmaxf(mm, part[c * NC + col]);
        agg[col] = mm;
    }
}

// sterm = bias + agg @ Wlow  (Wlow row stride == NC), k split across segs.
template <int NC, int KA>
__device__ __forceinline__ void sterm_calc(const float* __restrict__ Wlow,
                                           const float* __restrict__ bg,
                                           const float* __restrict__ agg,
                                           float* __restrict__ part,
                                           float* __restrict__ sterm, int ltid, int hp)
{
    constexpr int NSEG = 256 / NC;
    constexpr int KS   = KA / NSEG;
    const int col = ltid % NC, seg = ltid / NC;
    float s = 0.f;
#pragma unroll
    for (int k = 0; k < KS; k++)
        s = fmaf(agg[seg * KS + k], Wlow[(seg * KS + k) * NC + col], s);
    part[seg * NC + col] = s;
    hbar(hp);
    if (ltid < NC) {
        float v = bg[col];
#pragma unroll
        for (int c = 0; c < NSEG; c++) v += part[c * NC + col];
        sterm[col] = v;
    }
}

// ---------------------------------------------------------------------------
// Persistent main kernel: grid=148, 512 threads = two decoupled 256-thr halves.
// Per-half smem: bufA (x0/h1, LD36|68) 4352, bufB (h0 / L2-max partials) 2304,
// agg 128, sterm 128, part 256  -> 7168 floats.
// ---------------------------------------------------------------------------
__global__ void __launch_bounds__(512, 1)
vn_main_kernel(const float* __restrict__ data,
               const float* __restrict__ W0g, const float* __restrict__ b0g,
               const float* __restrict__ g0g, const float* __restrict__ be0g,
               const float* __restrict__ W1g, const float* __restrict__ b1g,
               const float* __restrict__ g1g, const float* __restrict__ be1g,
               const float* __restrict__ W2g, const float* __restrict__ b2g,
               const float* __restrict__ g2g, const float* __restrict__ be2g)
{
    extern __shared__ float sm[];
    float* W0s  = sm;            // 1024
    float* W1s  = sm + 1024;     // 4096
    float* W2s  = sm + 5120;     // 16384
    float* g0s  = sm + 21504;  float* be0s = sm + 21536;
    float* g1s  = sm + 21568;  float* be1s = sm + 21632;
    float* g2s  = sm + 21696;  float* be2s = sm + 21824;
    float* b0s  = sm + 21952;  float* b1s  = sm + 21984;
    float* b2s  = sm + 22048;  // weights end at 22176

    const int tid  = threadIdx.x;
    const int hp   = tid >> 8;        // which half (poly of the pair)
    const int ltid = tid & 255;

    float* pb    = sm + 22176 + hp * 7168;
    float* bufA  = pb;           // 4352: x0 @LD36, then h1 @LD68
    float* bufB  = pb + 4352;    // 2304: h0 @LD36; reused as L2 max partials (16x128)
    float* agg   = pb + 6656;    // 128
    float* sterm = pb + 6784;    // 128
    float* part  = pb + 6912;    // 256

    // stage weights once per block (block-wide)
    for (int i = tid; i < 256;  i += 512) ((float4*)W0s)[i] = ((const float4*)W0g)[i];
    for (int i = tid; i < 1024; i += 512) ((float4*)W1s)[i] = ((const float4*)W1g)[i];
    for (int i = tid; i < 4096; i += 512) ((float4*)W2s)[i] = ((const float4*)W2g)[i];
    if (tid < 32)  { g0s[tid] = g0g[tid]; be0s[tid] = be0g[tid]; b0s[tid] = b0g[tid]; }
    else if (tid < 96)  { g1s[tid-32] = g1g[tid-32]; be1s[tid-32] = be1g[tid-32]; b1s[tid-32] = b1g[tid-32]; }
    else if (tid < 224) { g2s[tid-96] = g2g[tid-96]; be2s[tid-96] = be2g[tid-96]; b2s[tid-96] = b2g[tid-96]; }
    __syncthreads();   // only block-wide sync; halves free-run after this

    // ---- initial x0 load for first tile ----
    {
        const int pair = blockIdx.x;
        const int b    = pair >> 7;
        const int poly = ((pair & 127) << 1) + hp;
        const float* base = data + ((size_t)b * 16385 + 1 + (size_t)poly * 64) * 32;
#pragma unroll
        for (int t = 0; t < 2; t++) {
            int e4 = ltid + t * 256;
            float4 v = ((const float4*)base)[e4];
            int r = e4 >> 3, kq = e4 & 7;
            if (kq == 7) v.w = 0.f;
            *reinterpret_cast<float4*>(bufA + r * 36 + kq * 4) = v;
        }
    }
    hbar(hp);

    for (int pair = blockIdx.x; pair < NPAIRS; pair += MAIN_GRID) {
        const int b    = pair >> 7;
        const int poly = ((pair & 127) << 1) + hp;

        // ---- layer 0 ----  (bufA: x0 -> bufB: h0)
        gemm_ln_relu<32, 32, 1, 36, 36, true>(bufA, bufB, W0s, g0s, be0s, b0s, ltid);
        hbar(hp);
        colmax<32, 36>(bufB, part, agg, ltid, hp);
        hbar(hp);

        // ---- layer 1 ----  (bufB: h0 -> bufA: h1)
        sterm_calc<64, 32>(W1s + 32 * 64, b1s, agg, part, sterm, ltid, hp);
        hbar(hp);
        gemm_ln_relu<32, 64, 2, 36, 68, true>(bufB, bufA, W1s, g1s, be1s, sterm, ltid);
        hbar(hp);
        colmax<64, 68>(bufA, part, agg, ltid, hp);
        hbar(hp);

        // ---- layer 2 ----  (bufA: h1 -> row-max partials in bufB)
        sterm_calc<128, 64>(W2s + 64 * 128, b2s, agg, part, sterm, ltid, hp);
        hbar(hp);

        // prefetch next tile's x0 into registers (hidden behind L2 GEMM)
        int np = pair + MAIN_GRID;
        if (np >= NPAIRS) np = pair;           // harmless reload on last tile
        const int nb    = np >> 7;
        const int npoly = ((np & 127) << 1) + hp;
        const float* nbase = data + ((size_t)nb * 16385 + 1 + (size_t)npoly * 64) * 32;
        float4 xp0 = ((const float4*)nbase)[ltid];
        float4 xp1 = ((const float4*)nbase)[ltid + 256];

        gemm_ln_relu<64, 128, 4, 68, 128, false>(bufA, bufB, W2s, g2s, be2s, sterm, ltid);
        hbar(hp);

        // reduce 16 row-group partials -> agg2 -> g_agg
        if (ltid < 128) {
            float m = bufB[ltid];
#pragma unroll
            for (int r = 1; r < 16; r++) m = fmaxf(m, bufB[r * 128 + ltid]);
            g_agg[((size_t)(b * 256 + poly)) * 128 + ltid] = m;
        }

        // store prefetched x0 into bufA (L2 GEMM done reading h1)
        {
            int e4 = ltid;
            int r = e4 >> 3, kq = e4 & 7;
            if (kq == 7) xp0.w = 0.f;
            *reinterpret_cast<float4*>(bufA + r * 36 + kq * 4) = xp0;
            e4 = ltid + 256;
            r = e4 >> 3; kq = e4 & 7;
            if (kq == 7) xp1.w = 0.f;
            *reinterpret_cast<float4*>(bufA + r * 36 + kq * 4) = xp1;
        }
        hbar(hp);
    }
}

// ---------------------------------------------------------------------------
// Attention kernel: one block per batch, 512 threads, split partials.
// q = P[agent]@Wq'+bq; t = Wk'q; scores = P@t/16; softmax; out = (att@P)@Wv'+bv
// (Wx' = Wx[:128]+Wx[128:] since P halves are identical; bk drops in softmax)
// ---------------------------------------------------------------------------
__global__ void __launch_bounds__(512, 1)
vn_attn_kernel(const float* __restrict__ data,
               const float* __restrict__ Wq, const float* __restrict__ bq,
               const float* __restrict__ Wk,
               const float* __restrict__ Wv, const float* __restrict__ bv,
               float* __restrict__ out)
{
    extern __shared__ float sm[];
    float* Pb   = sm;            // 256*132 = 33792
    float* q    = Pb + 33792;    // 256
    float* t    = q + 256;       // 128
    float* sc   = t + 128;       // 256
    float* w128 = sc + 256;      // 128
    float* red  = w128 + 128;    // 32
    float* part = red + 32;      // 512

    const int tid = threadIdx.x, lane = tid & 31, w = tid >> 5;
    const int b = blockIdx.x;

    const float* P = g_agg + (size_t)b * 256 * 128;
    for (int e4 = tid; e4 < 8192; e4 += 512) {
        int p = e4 >> 5, j4 = e4 & 31;
        *reinterpret_cast<float4*>(Pb + p * 132 + j4 * 4) = ((const float4*)P)[e4];
    }
    if (tid == 0) red[0] = data[(size_t)b * 16385 * 32];  // agent id
    __syncthreads();
    const int aid = (int)red[0];

    // q = P[agent] @ Wq' + bq  (k-split 2-way)
    {
        const int col = tid & 255, half = tid >> 8;
        const float* pr = Pb + aid * 132;
        float s = 0.f;
        for (int j = half * 64; j < half * 64 + 64; j++)
            s = fmaf(pr[j], Wq[j * 256 + col] + Wq[(j + 128) * 256 + col], s);
        part[half * 256 + col] = s;
    }
    __syncthreads();
    if (tid < 256) q[tid] = bq[tid] + part[tid] + part[256 + tid];
    __syncthreads();

    // t = Wk' @ q  (16 warps x 8 rows)
    for (int jj = 0; jj < 8; jj++) {
        int j = w * 8 + jj;
        float a = 0.f;
#pragma unroll
        for (int m = 0; m < 8; m++) {
            int c = lane + m * 32;
            a = fmaf(Wk[j * 256 + c] + Wk[(j + 128) * 256 + c], q[c], a);
        }
#pragma unroll
        for (int o = 16; o > 0; o >>= 1) a += __shfl_xor_sync(0xffffffffu, a, o);
        if (lane == 0) t[j] = a;
    }
    __syncthreads();

    // scores[p] = (P[p].t)/16  (16 warps x 16 rows)
    for (int pp = 0; pp < 16; pp++) {
        int p = w * 16 + pp;
        float a = 0.f;
#pragma unroll
        for (int m = 0; m < 4; m++) {
            int j = lane + m * 32;
            a = fmaf(Pb[p * 132 + j], t[j], a);
        }
#pragma unroll
        for (int o = 16; o > 0; o >>= 1) a += __shfl_xor_sync(0xffffffffu, a, o);
        if (lane == 0) sc[p] = a * 0.0625f;
    }
    __syncthreads();

    // softmax over 256 (threads 0..255)
    float v = 0.f, e = 0.f;
    if (tid < 256) {
        v = sc[tid];
        float mx = v;
#pragma unroll
        for (int o = 16; o > 0; o >>= 1) mx = fmaxf(mx, __shfl_xor_sync(0xffffffffu, mx, o));
        if (lane == 0) red[w] = mx;
    }
    __syncthreads();
    if (tid == 0) {
        float M = red[0];
        for (int i = 1; i < 8; i++) M = fmaxf(M, red[i]);
        red[8] = M;
    }
    __syncthreads();
    if (tid < 256) {
        e = __expf(v - red[8]);
        float se = e;
#pragma unroll
        for (int o = 16; o > 0; o >>= 1) se += __shfl_xor_sync(0xffffffffu, se, o);
        if (lane == 0) red[16 + w] = se;
    }
    __syncthreads();
    if (tid == 0) {
        float S = 0.f;
        for (int i = 0; i < 8; i++) S += red[16 + i];
        red[24] = 1.f / S;
    }
    __syncthreads();
    if (tid < 256) sc[tid] = e * red[24];
    __syncthreads();

    // w128 = att @ P  (4-way row split)
    {
        const int col = tid & 127, seg = tid >> 7;
        float a = 0.f;
        for (int p = seg * 64; p < seg * 64 + 64; p++)
            a = fmaf(sc[p], Pb[p * 132 + col], a);
        part[seg * 128 + col] = a;
    }
    __syncthreads();
    if (tid < 128)
        w128[tid] = part[tid] + part[128 + tid] + part[256 + tid] + part[384 + tid];
    __syncthreads();

    // out = w128 @ Wv' + bv  (k-split 2-way)
    {
        const int col = tid & 255, half = tid >> 8;
        float o = 0.f;
        for (int j = half * 64; j < half * 64 + 64; j++)
            o = fmaf(w128[j], Wv[j * 256 + col] + Wv[(j + 128) * 256 + col], o);
        part[half * 256 + col] = o;
    }
    __syncthreads();
    if (tid < 256) out[b * 256 + tid] = bv[tid] + part[tid] + part[256 + tid];
}

// ---------------------------------------------------------------------------
extern "C" void kernel_launch(void* const* d_in, const int* in_sizes, int n_in,
                              void* d_out, int out_size)
{
    const float* data = (const float*)d_in[0];
    const float* W0  = (const float*)d_in[1];
    const float* b0  = (const float*)d_in[2];
    const float* g0  = (const float*)d_in[3];
    const float* be0 = (const float*)d_in[4];
    const float* W1  = (const float*)d_in[5];
    const float* b1  = (const float*)d_in[6];
    const float* g1  = (const float*)d_in[7];
    const float* be1 = (const float*)d_in[8];
    const float* W2  = (const float*)d_in[9];
    const float* b2  = (const float*)d_in[10];
    const float* g2  = (const float*)d_in[11];
    const float* be2 = (const float*)d_in[12];
    const float* Wq  = (const float*)d_in[13];
    const float* bq  = (const float*)d_in[14];
    const float* Wk  = (const float*)d_in[15];
    // d_in[16] = bk: softmax-invariant, unused
    const float* Wv  = (const float*)d_in[17];
    const float* bv  = (const float*)d_in[18];
    float* out = (float*)d_out;

    const size_t smA = (size_t)(22176 + 2 * 7168) * sizeof(float);   // ~142.6 KB
    const size_t smB = (size_t)(33792 + 256 + 128 + 256 + 128 + 32 + 512) * sizeof(float);
    cudaFuncSetAttribute(vn_main_kernel, cudaFuncAttributeMaxDynamicSharedMemorySize, (int)smA);
    cudaFuncSetAttribute(vn_attn_kernel, cudaFuncAttributeMaxDynamicSharedMemorySize, (int)smB);

    vn_main_kernel<<<MAIN_GRID, 512, smA>>>(data, W0, b0, g0, be0,
                                            W1, b1, g1, be1, W2, b2, g2, be2);
    vn_attn_kernel<<<NB, 512, smB>>>(data, Wq, bq, Wk, Wv, bv, out);
}

// round 11
// speedup vs baseline: 2.3799x; 1.5200x over previous
#include <cuda_runtime.h>

// VectorNet fused, round 9: persistent blocks, 512 thr = two 256-thr halves,
// each half processes TWO polylines per tile as a stacked 128-row GEMM.
// Epilogue phases amortized over 2 polys; 10 named barriers / 2 polys.
// B=32, NPOLY=256, VPP=64, L=32, PLEN=256

#define NB 32
#define NPOLY_ 256
#define NQUADS 2048   // 32 batches * 64 quads (4 polys per block-tile)
#define MAIN_GRID 148

__device__ float g_agg[NB * NPOLY_ * 128];  // 4 MB scratch

// half-local barrier: 256 threads, barrier id 1 or 2
__device__ __forceinline__ void hbar(int hp) {
    asm volatile("bar.sync %0, 256;" :: "r"(hp + 1) : "memory");
}

// ---------------------------------------------------------------------------
// Stacked GEMM: (128 x OUT_C) = x(128 x K) @ W(K x OUT_C) + sterm(poly),
// then LayerNorm+ReLU. 256 threads. Thread tile R rows x 8 cols; rows of one
// thread lie in a single poly (R <= 64 and divides 64).
// STORE=true : write h to hs (row stride HLD).
// STORE=false: per-thread row-max only -> hs[rg*HLD + c0..] (partials).
// st: sterm base; per-poly stride ST_STRIDE (0 => shared bias).
// ---------------------------------------------------------------------------
template <int K, int OUT_C, int R, int XLD, int HLD, bool STORE, int ST_STRIDE>
__device__ __forceinline__ void gemm_ln_relu(
    const float* __restrict__ xs, float* __restrict__ hs,
    const float* __restrict__ Ws, const float* __restrict__ gs,
    const float* __restrict__ bes, const float* __restrict__ st, int ltid)
{
    constexpr int NCG = OUT_C / 8;       // col groups
    constexpr int RG  = (R > 4) ? 4 : R; // rows loaded per x-group (reg cap)
    constexpr int NG  = R / RG;
    const int rg = ltid / NCG, cg = ltid % NCG;
    const int r0 = rg * R, c0 = cg * 8;
    const int poly = r0 >> 6;
    const float* sb = st + poly * ST_STRIDE;

    float acc[R][8];
#pragma unroll
    for (int i = 0; i < R; i++)
#pragma unroll
        for (int j = 0; j < 8; j++) acc[i][j] = sb[c0 + j];

#pragma unroll 2
    for (int k0 = 0; k0 < K; k0 += 4) {
#pragma unroll
        for (int g = 0; g < NG; g++) {
            float xv[RG][4];
#pragma unroll
            for (int i = 0; i < RG; i++) {
                float4 t = *reinterpret_cast<const float4*>(
                    xs + (r0 + g * RG + i) * XLD + k0);
                xv[i][0] = t.x; xv[i][1] = t.y; xv[i][2] = t.z; xv[i][3] = t.w;
            }
#pragma unroll
            for (int kk = 0; kk < 4; kk++) {
                float4 wa = *reinterpret_cast<const float4*>(Ws + (k0 + kk) * OUT_C + c0);
                float4 wb = *reinterpret_cast<const float4*>(Ws + (k0 + kk) * OUT_C + c0 + 4);
#pragma unroll
                for (int i = 0; i < RG; i++) {
                    float x = xv[i][kk];
                    float* a = acc[g * RG + i];
                    a[0] = fmaf(x, wa.x, a[0]);
                    a[1] = fmaf(x, wa.y, a[1]);
                    a[2] = fmaf(x, wa.z, a[2]);
                    a[3] = fmaf(x, wa.w, a[3]);
                    a[4] = fmaf(x, wb.x, a[4]);
                    a[5] = fmaf(x, wb.y, a[5]);
                    a[6] = fmaf(x, wb.z, a[6]);
                    a[7] = fmaf(x, wb.w, a[7]);
                }
            }
        }
    }

    const float invC = 1.0f / (float)OUT_C;
    float mx[8];
    if (!STORE) {
#pragma unroll
        for (int j = 0; j < 8; j++) mx[j] = 0.f;
    }

#pragma unroll
    for (int i = 0; i < R; i++) {
        float s = 0.f, s2 = 0.f;
#pragma unroll
        for (int j = 0; j < 8; j++) {
            s += acc[i][j];
            s2 = fmaf(acc[i][j], acc[i][j], s2);
        }
#pragma unroll
        for (int o = NCG / 2; o > 0; o >>= 1) {
            s  += __shfl_xor_sync(0xffffffffu, s, o);
            s2 += __shfl_xor_sync(0xffffffffu, s2, o);
        }
        float mu   = s * invC;
        float var  = fmaf(-mu, mu, s2 * invC);
        float rstd = rsqrtf(var + 1e-5f);
        float v[8];
#pragma unroll
        for (int j = 0; j < 8; j++)
            v[j] = fmaxf(fmaf((acc[i][j] - mu) * rstd, gs[c0 + j], bes[c0 + j]), 0.f);

        if (STORE) {
            float4 o1 = {v[0], v[1], v[2], v[3]};
            float4 o2 = {v[4], v[5], v[6], v[7]};
            *reinterpret_cast<float4*>(hs + (r0 + i) * HLD + c0)     = o1;
            *reinterpret_cast<float4*>(hs + (r0 + i) * HLD + c0 + 4) = o2;
        } else {
#pragma unroll
            for (int j = 0; j < 8; j++) mx[j] = fmaxf(mx[j], v[j]);
        }
    }

    if (!STORE) {
        float4 m1 = {mx[0], mx[1], mx[2], mx[3]};
        float4 m2 = {mx[4], mx[5], mx[6], mx[7]};
        *reinterpret_cast<float4*>(hs + rg * HLD + c0)     = m1;
        *reinterpret_cast<float4*>(hs + rg * HLD + c0 + 4) = m2;
    }
}

// colmax partial pass over 128 stacked rows (post-ReLU, >= 0)
template <int NC, int LD>
__device__ __forceinline__ void colmax_part(const float* __restrict__ hs,
                                            float* __restrict__ part, int ltid)
{
    constexpr int NCH = 256 / NC;     // chunks (first half poly0, second poly1)
    constexpr int RP  = 128 / NCH;    // rows per chunk
    const int col = ltid % NC, ch = ltid / NC;
    float m = 0.f;
#pragma unroll
    for (int r = 0; r < RP; r++) m = fmaxf(m, hs[(ch * RP + r) * LD + col]);
    part[ch * NC + col] = m;
}

// ---------------------------------------------------------------------------
// Persistent main kernel: grid=148, 512 threads = two decoupled 256-thr
// halves; each half runs 2 polys per tile (stacked 128-row GEMMs).
// Per-half smem floats: bufA 8704 (x0 LD36 / h1 LD68), bufB 4608 (h0 LD36 /
// L2 max partials 16x128), agg 256, sterm 256, part 256  -> 14080.
// ---------------------------------------------------------------------------
__global__ void __launch_bounds__(512, 1)
vn_main_kernel(const float* __restrict__ data,
               const float* __restrict__ W0g, const float* __restrict__ b0g,
               const float* __restrict__ g0g, const float* __restrict__ be0g,
               const float* __restrict__ W1g, const float* __restrict__ b1g,
               const float* __restrict__ g1g, const float* __restrict__ be1g,
               const float* __restrict__ W2g, const float* __restrict__ b2g,
               const float* __restrict__ g2g, const float* __restrict__ be2g)
{
    extern __shared__ float sm[];
    float* W0s  = sm;            // 1024
    float* W1s  = sm + 1024;     // 4096
    float* W2s  = sm + 5120;     // 16384
    float* g0s  = sm + 21504;  float* be0s = sm + 21536;
    float* g1s  = sm + 21568;  float* be1s = sm + 21632;
    float* g2s  = sm + 21696;  float* be2s = sm + 21824;
    float* b0s  = sm + 21952;  float* b1s  = sm + 21984;
    float* b2s  = sm + 22048;  // weights end at 22176

    const int tid  = threadIdx.x;
    const int hp   = tid >> 8;        // which half
    const int ltid = tid & 255;

    float* pb    = sm + 22176 + hp * 14080;
    float* bufA  = pb;           // 8704: x0 @LD36 then h1 @LD68 (128 rows)
    float* bufB  = pb + 8704;    // 4608: h0 @LD36; reused as L2 partials 16x128
    float* agg   = pb + 13312;   // 256 (2 polys)
    float* sterm = pb + 13568;   // 256 (2 polys)
    float* part  = pb + 13824;   // 256

    // stage weights once per block (block-wide)
    for (int i = tid; i < 256;  i += 512) ((float4*)W0s)[i] = ((const float4*)W0g)[i];
    for (int i = tid; i < 1024; i += 512) ((float4*)W1s)[i] = ((const float4*)W1g)[i];
    for (int i = tid; i < 4096; i += 512) ((float4*)W2s)[i] = ((const float4*)W2g)[i];
    if (tid < 32)  { g0s[tid] = g0g[tid]; be0s[tid] = be0g[tid]; b0s[tid] = b0g[tid]; }
    else if (tid < 96)  { g1s[tid-32] = g1g[tid-32]; be1s[tid-32] = be1g[tid-32]; b1s[tid-32] = b1g[tid-32]; }
    else if (tid < 224) { g2s[tid-96] = g2g[tid-96]; be2s[tid-96] = be2g[tid-96]; b2s[tid-96] = b2g[tid-96]; }
    __syncthreads();   // only block-wide sync; halves free-run after this

    // ---- initial x0 load: 2 polys = 128 rows x 32 ch, channel 31 zeroed ----
    {
        const int quad = blockIdx.x;
        const int b = quad >> 6, qi = quad & 63;
        const int poly0 = qi * 4 + hp * 2;
        const float* base = data + ((size_t)b * 16385 + 1 + (size_t)poly0 * 64) * 32;
#pragma unroll
        for (int t = 0; t < 4; t++) {
            int e4 = ltid + t * 256;
            float4 v = ((const float4*)base)[e4];
            int r = e4 >> 3, kq = e4 & 7;
            if (kq == 7) v.w = 0.f;
            *reinterpret_cast<float4*>(bufA + r * 36 + kq * 4) = v;
        }
    }
    hbar(hp);

    for (int quad = blockIdx.x; quad < NQUADS; quad += MAIN_GRID) {
        const int b = quad >> 6, qi = quad & 63;
        const int poly0 = qi * 4 + hp * 2;

        // ---- layer 0 ----  (bufA x0 LD36 -> bufB h0 LD36), sterm = b0 shared
        gemm_ln_relu<32, 32, 2, 36, 36, true, 0>(bufA, bufB, W0s, g0s, be0s, b0s, ltid);
        hbar(hp);
        colmax_part<32, 36>(bufB, part, ltid);          // 8 chunks x 32
        hbar(hp);
        if (ltid < 64) {                                 // agg0[poly*32+col]
            int poly = ltid >> 5, col = ltid & 31;
            float m = part[(poly * 4) * 32 + col];
#pragma unroll
            for (int c = 1; c < 4; c++) m = fmaxf(m, part[(poly * 4 + c) * 32 + col]);
            agg[poly * 32 + col] = m;
        }
        hbar(hp);
        if (ltid < 128) {                                // sterm1 = b1 + agg0 @ W1low
            int poly = ltid >> 6, col = ltid & 63;
            float v = b1s[col];
#pragma unroll
            for (int k = 0; k < 32; k++)
                v = fmaf(agg[poly * 32 + k], W1s[(32 + k) * 64 + col], v);
            sterm[poly * 64 + col] = v;
        }
        hbar(hp);

        // ---- layer 1 ----  (bufB h0 LD36 -> bufA h1 LD68)
        gemm_ln_relu<32, 64, 4, 36, 68, true, 64>(bufB, bufA, W1s, g1s, be1s, sterm, ltid);
        hbar(hp);
        colmax_part<64, 68>(bufA, part, ltid);          // 4 chunks x 64
        hbar(hp);
        if (ltid < 128) {                                // agg1[poly*64+col]
            int poly = ltid >> 6, col = ltid & 63;
            agg[poly * 64 + col] =
                fmaxf(part[(poly * 2) * 64 + col], part[(poly * 2 + 1) * 64 + col]);
        }
        hbar(hp);
        {                                                // sterm2 = b2 + agg1 @ W2low
            int poly = ltid >> 7, col = ltid & 127;
            float v = b2s[col];
#pragma unroll
            for (int k = 0; k < 64; k++)
                v = fmaf(agg[poly * 64 + k], W2s[(64 + k) * 128 + col], v);
            sterm[ltid] = v;
        }
        hbar(hp);

        // ---- layer 2 ----  (bufA h1 LD68 -> bufB rowgroup max partials 16x128)
        gemm_ln_relu<64, 128, 8, 68, 128, false, 128>(bufA, bufB, W2s, g2s, be2s, sterm, ltid);
        hbar(hp);

        // ---- final phase: next x0 LDG issue, agg2 reduce+store, x0 STS ----
        int nq = quad + MAIN_GRID;
        if (nq >= NQUADS) nq = quad;                    // harmless reload on last
        const int nb = nq >> 6, nqi = nq & 63;
        const int npoly0 = nqi * 4 + hp * 2;
        const float* nbase = data + ((size_t)nb * 16385 + 1 + (size_t)npoly0 * 64) * 32;
        float4 xp[4];
#pragma unroll
        for (int t = 0; t < 4; t++) xp[t] = ((const float4*)nbase)[ltid + t * 256];

        {   // agg2 over 8 rowgroups per poly -> g_agg
            int poly = ltid >> 7, col = ltid & 127;
            float m = bufB[(poly * 8) * 128 + col];
#pragma unroll
            for (int r = 1; r < 8; r++) m = fmaxf(m, bufB[(poly * 8 + r) * 128 + col]);
            g_agg[((size_t)(b * 256 + poly0 + poly)) * 128 + col] = m;
        }

#pragma unroll
        for (int t = 0; t < 4; t++) {
            int e4 = ltid + t * 256;
            int r = e4 >> 3, kq = e4 & 7;
            if (kq == 7) xp[t].w = 0.f;
            *reinterpret_cast<float4*>(bufA + r * 36 + kq * 4) = xp[t];
        }
        hbar(hp);
    }
}

// ---------------------------------------------------------------------------
// Attention kernel: one block per batch, 512 threads, split partials.
// q = P[agent]@Wq'+bq; t = Wk'q; scores = P@t/16; softmax; out = (att@P)@Wv'+bv
// (Wx' = Wx[:128]+Wx[128:] since P halves are identical; bk drops in softmax)
// ---------------------------------------------------------------------------
__global__ void __launch_bounds__(512, 1)
vn_attn_kernel(const float* __restrict__ data,
               const float* __restrict__ Wq, const float* __restrict__ bq,
               const float* __restrict__ Wk,
               const float* __restrict__ Wv, const float* __restrict__ bv,
               float* __restrict__ out)
{
    extern __shared__ float sm[];
    float* Pb   = sm;            // 256*132 = 33792
    float* q    = Pb + 33792;    // 256
    float* t    = q + 256;       // 128
    float* sc   = t + 128;       // 256
    float* w128 = sc + 256;      // 128
    float* red  = w128 + 128;    // 32
    float* part = red + 32;      // 512

    const int tid = threadIdx.x, lane = tid & 31, w = tid >> 5;
    const int b = blockIdx.x;

    const float* P = g_agg + (size_t)b * 256 * 128;
    for (int e4 = tid; e4 < 8192; e4 += 512) {
        int p = e4 >> 5, j4 = e4 & 31;
        *reinterpret_cast<float4*>(Pb + p * 132 + j4 * 4) = ((const float4*)P)[e4];
    }
    if (tid == 0) red[0] = data[(size_t)b * 16385 * 32];  // agent id
    __syncthreads();
    const int aid = (int)red[0];

    // q = P[agent] @ Wq' + bq  (k-split 2-way)
    {
        const int col = tid & 255, half = tid >> 8;
        const float* pr = Pb + aid * 132;
        float s = 0.f;
        for (int j = half * 64; j < half * 64 + 64; j++)
            s = fmaf(pr[j], Wq[j * 256 + col] + Wq[(j + 128) * 256 + col], s);
        part[half * 256 + col] = s;
    }
    __syncthreads();
    if (tid < 256) q[tid] = bq[tid] + part[tid] + part[256 + tid];
    __syncthreads();

    // t = Wk' @ q  (16 warps x 8 rows)
    for (int jj = 0; jj < 8; jj++) {
        int j = w * 8 + jj;
        float a = 0.f;
#pragma unroll
        for (int m = 0; m < 8; m++) {
            int c = lane + m * 32;
            a = fmaf(Wk[j * 256 + c] + Wk[(j + 128) * 256 + c], q[c], a);
        }
#pragma unroll
        for (int o = 16; o > 0; o >>= 1) a += __shfl_xor_sync(0xffffffffu, a, o);
        if (lane == 0) t[j] = a;
    }
    __syncthreads();

    // scores[p] = (P[p].t)/16  (16 warps x 16 rows)
    for (int pp = 0; pp < 16; pp++) {
        int p = w * 16 + pp;
        float a = 0.f;
#pragma unroll
        for (int m = 0; m < 4; m++) {
            int j = lane + m * 32;
            a = fmaf(Pb[p * 132 + j], t[j], a);
        }
#pragma unroll
        for (int o = 16; o > 0; o >>= 1) a += __shfl_xor_sync(0xffffffffu, a, o);
        if (lane == 0) sc[p] = a * 0.0625f;
    }
    __syncthreads();

    // softmax over 256 (threads 0..255)
    float v = 0.f, e = 0.f;
    if (tid < 256) {
        v = sc[tid];
        float mx = v;
#pragma unroll
        for (int o = 16; o > 0; o >>= 1) mx = fmaxf(mx, __shfl_xor_sync(0xffffffffu, mx, o));
        if (lane == 0) red[w] = mx;
    }
    __syncthreads();
    if (tid == 0) {
        float M = red[0];
        for (int i = 1; i < 8; i++) M = fmaxf(M, red[i]);
        red[8] = M;
    }
    __syncthreads();
    if (tid < 256) {
        e = __expf(v - red[8]);
        float se = e;
#pragma unroll
        for (int o = 16; o > 0; o >>= 1) se += __shfl_xor_sync(0xffffffffu, se, o);
        if (lane == 0) red[16 + w] = se;
    }
    __syncthreads();
    if (tid == 0) {
        float S = 0.f;
        for (int i = 0; i < 8; i++) S += red[16 + i];
        red[24] = 1.f / S;
    }
    __syncthreads();
    if (tid < 256) sc[tid] = e * red[24];
    __syncthreads();

    // w128 = att @ P  (4-way row split)
    {
        const int col = tid & 127, seg = tid >> 7;
        float a = 0.f;
        for (int p = seg * 64; p < seg * 64 + 64; p++)
            a = fmaf(sc[p], Pb[p * 132 + col], a);
        part[seg * 128 + col] = a;
    }
    __syncthreads();
    if (tid < 128)
        w128[tid] = part[tid] + part[128 + tid] + part[256 + tid] + part[384 + tid];
    __syncthreads();

    // out = w128 @ Wv' + bv  (k-split 2-way)
    {
        const int col = tid & 255, half = tid >> 8;
        float o = 0.f;
        for (int j = half * 64; j < half * 64 + 64; j++)
            o = fmaf(w128[j], Wv[j * 256 + col] + Wv[(j + 128) * 256 + col], o);
        part[half * 256 + col] = o;
    }
    __syncthreads();
    if (tid < 256) out[b * 256 + tid] = bv[tid] + part[tid] + part[256 + tid];
}

// ---------------------------------------------------------------------------
extern "C" void kernel_launch(void* const* d_in, const int* in_sizes, int n_in,
                              void* d_out, int out_size)
{
    const float* data = (const float*)d_in[0];
    const float* W0  = (const float*)d_in[1];
    const float* b0  = (const float*)d_in[2];
    const float* g0  = (const float*)d_in[3];
    const float* be0 = (const float*)d_in[4];
    const float* W1  = (const float*)d_in[5];
    const float* b1  = (const float*)d_in[6];
    const float* g1  = (const float*)d_in[7];
    const float* be1 = (const float*)d_in[8];
    const float* W2  = (const float*)d_in[9];
    const float* b2  = (const float*)d_in[10];
    const float* g2  = (const float*)d_in[11];
    const float* be2 = (const float*)d_in[12];
    const float* Wq  = (const float*)d_in[13];
    const float* bq  = (const float*)d_in[14];
    const float* Wk  = (const float*)d_in[15];
    // d_in[16] = bk: softmax-invariant, unused
    const float* Wv  = (const float*)d_in[17];
    const float* bv  = (const float*)d_in[18];
    float* out = (float*)d_out;

    const size_t smA = (size_t)(22176 + 2 * 14080) * sizeof(float);  // ~196.6 KB
    const size_t smB = (size_t)(33792 + 256 + 128 + 256 + 128 + 32 + 512) * sizeof(float);
    cudaFuncSetAttribute(vn_main_kernel, cudaFuncAttributeMaxDynamicSharedMemorySize, (int)smA);
    cudaFuncSetAttribute(vn_attn_kernel, cudaFuncAttributeMaxDynamicSharedMemorySize, (int)smB);

    vn_main_kernel<<<MAIN_GRID, 512, smA>>>(data, W0, b0, g0, be0,
                                            W1, b1, g1, be1, W2, b2, g2, be2);
    vn_attn_kernel<<<NB, 512, smB>>>(data, Wq, bq, Wk, Wv, bv, out);
}

// round 12
// speedup vs baseline: 2.4824x; 1.0431x over previous
#include <cuda_runtime.h>

// VectorNet fused, round 11: R9 structure + packed fp32 GEMM (fma.rn.f32x2 /
// SASS FFMA2, 2 fp32 FMAs per issue slot). Bit-exact vs scalar fp32.
// Persistent blocks, 512 thr = two 256-thr halves, 2 polys/half/tile.
// B=32, NPOLY=256, VPP=64, L=32, PLEN=256

#define NB 32
#define NPOLY_ 256
#define NQUADS 2048   // 32 batches * 64 quads (4 polys per block-tile)
#define MAIN_GRID 148

typedef unsigned long long u64;

__device__ float g_agg[NB * NPOLY_ * 128];  // 4 MB scratch

// packed helpers
#define FMA2(d, x, w) \
    asm("fma.rn.f32x2 %0, %1, %2, %0;" : "+l"(d) : "l"(x), "l"(w))
#define PACK2(dst, f) \
    asm("mov.b64 %0, {%1, %1};" : "=l"(dst) : "f"(f))
#define UNPACK2(lo, hi, v) \
    asm("mov.b64 {%0, %1}, %2;" : "=f"(lo), "=f"(hi) : "l"(v))

// half-local barrier: 256 threads, barrier id 1 or 2
__device__ __forceinline__ void hbar(int hp) {
    asm volatile("bar.sync %0, 256;" :: "r"(hp + 1) : "memory");
}

// ---------------------------------------------------------------------------
// Stacked GEMM: (128 x OUT_C) = x(128 x K) @ W(K x OUT_C) + sterm(poly),
// then LayerNorm+ReLU. 256 threads. Thread tile R rows x 8 cols (4 col-pairs,
// packed f32x2). Rows of one thread lie in a single poly.
// STORE=true : write h to hs (row stride HLD).
// STORE=false: per-thread row-max only -> hs[rg*HLD + c0..] (partials).
// st: sterm base; per-poly stride ST_STRIDE (0 => shared bias).
// ---------------------------------------------------------------------------
template <int K, int OUT_C, int R, int XLD, int HLD, bool STORE, int ST_STRIDE>
__device__ __forceinline__ void gemm_ln_relu(
    const float* __restrict__ xs, float* __restrict__ hs,
    const float* __restrict__ Ws, const float* __restrict__ gs,
    const float* __restrict__ bes, const float* __restrict__ st, int ltid)
{
    constexpr int NCG = OUT_C / 8;       // col groups
    constexpr int RG  = (R > 4) ? 4 : R; // rows per x-load group (reg cap)
    constexpr int NG  = R / RG;
    const int rg = ltid / NCG, cg = ltid % NCG;
    const int r0 = rg * R, c0 = cg * 8;
    const int poly = r0 >> 6;
    const float* sb = st + poly * ST_STRIDE;

    u64 acc[R][4];                        // 4 packed col-pairs per row
    {
        ulonglong2 s01 = *reinterpret_cast<const ulonglong2*>(sb + c0);
        ulonglong2 s23 = *reinterpret_cast<const ulonglong2*>(sb + c0 + 4);
#pragma unroll
        for (int i = 0; i < R; i++) {
            acc[i][0] = s01.x; acc[i][1] = s01.y;
            acc[i][2] = s23.x; acc[i][3] = s23.y;
        }
    }

#pragma unroll 2
    for (int k0 = 0; k0 < K; k0 += 4) {
#pragma unroll
        for (int g = 0; g < NG; g++) {
            float xv[RG][4];
#pragma unroll
            for (int i = 0; i < RG; i++) {
                float4 t = *reinterpret_cast<const float4*>(
                    xs + (r0 + g * RG + i) * XLD + k0);
                xv[i][0] = t.x; xv[i][1] = t.y; xv[i][2] = t.z; xv[i][3] = t.w;
            }
#pragma unroll
            for (int kk = 0; kk < 4; kk++) {
                ulonglong2 wA = *reinterpret_cast<const ulonglong2*>(
                    Ws + (k0 + kk) * OUT_C + c0);
                ulonglong2 wB = *reinterpret_cast<const ulonglong2*>(
                    Ws + (k0 + kk) * OUT_C + c0 + 4);
#pragma unroll
                for (int i = 0; i < RG; i++) {
                    u64 xx;
                    PACK2(xx, xv[i][kk]);
                    u64* a = acc[g * RG + i];
                    FMA2(a[0], xx, wA.x);
                    FMA2(a[1], xx, wA.y);
                    FMA2(a[2], xx, wB.x);
                    FMA2(a[3], xx, wB.y);
                }
            }
        }
    }

    const float invC = 1.0f / (float)OUT_C;
    float mx[8];
    if (!STORE) {
#pragma unroll
        for (int j = 0; j < 8; j++) mx[j] = 0.f;
    }

#pragma unroll
    for (int i = 0; i < R; i++) {
        float a[8];
#pragma unroll
        for (int j = 0; j < 4; j++) UNPACK2(a[2 * j], a[2 * j + 1], acc[i][j]);

        float s = 0.f, s2 = 0.f;
#pragma unroll
        for (int j = 0; j < 8; j++) {
            s += a[j];
            s2 = fmaf(a[j], a[j], s2);
        }
#pragma unroll
        for (int o = NCG / 2; o > 0; o >>= 1) {
            s  += __shfl_xor_sync(0xffffffffu, s, o);
            s2 += __shfl_xor_sync(0xffffffffu, s2, o);
        }
        float mu   = s * invC;
        float var  = fmaf(-mu, mu, s2 * invC);
        float rstd = rsqrtf(var + 1e-5f);
        float v[8];
#pragma unroll
        for (int j = 0; j < 8; j++)
            v[j] = fmaxf(fmaf((a[j] - mu) * rstd, gs[c0 + j], bes[c0 + j]), 0.f);

        if (STORE) {
            float4 o1 = {v[0], v[1], v[2], v[3]};
            float4 o2 = {v[4], v[5], v[6], v[7]};
            *reinterpret_cast<float4*>(hs + (r0 + i) * HLD + c0)     = o1;
            *reinterpret_cast<float4*>(hs + (r0 + i) * HLD + c0 + 4) = o2;
        } else {
#pragma unroll
            for (int j = 0; j < 8; j++) mx[j] = fmaxf(mx[j], v[j]);
        }
    }

    if (!STORE) {
        float4 m1 = {mx[0], mx[1], mx[2], mx[3]};
        float4 m2 = {mx[4], mx[5], mx[6], mx[7]};
        *reinterpret_cast<float4*>(hs + rg * HLD + c0)     = m1;
        *reinterpret_cast<float4*>(hs + rg * HLD + c0 + 4) = m2;
    }
}

// colmax partial pass over 128 stacked rows (post-ReLU, >= 0)
template <int NC, int LD>
__device__ __forceinline__ void colmax_part(const float* __restrict__ hs,
                                            float* __restrict__ part, int ltid)
{
    constexpr int NCH = 256 / NC;     // chunks (first half poly0, second poly1)
    constexpr int RP  = 128 / NCH;    // rows per chunk
    const int col = ltid % NC, ch = ltid / NC;
    float m = 0.f;
#pragma unroll
    for (int r = 0; r < RP; r++) m = fmaxf(m, hs[(ch * RP + r) * LD + col]);
    part[ch * NC + col] = m;
}

// ---------------------------------------------------------------------------
// Persistent main kernel: grid=148, 512 threads = two decoupled 256-thr
// halves; each half runs 2 polys per tile (stacked 128-row GEMMs).
// Per-half smem floats: bufA 8704 (x0 LD36 / h1 LD68), bufB 4608 (h0 LD36 /
// L2 max partials 16x128), agg 256, sterm 256, part 256  -> 14080.
// ---------------------------------------------------------------------------
__global__ void __launch_bounds__(512, 1)
vn_main_kernel(const float* __restrict__ data,
               const float* __restrict__ W0g, const float* __restrict__ b0g,
               const float* __restrict__ g0g, const float* __restrict__ be0g,
               const float* __restrict__ W1g, const float* __restrict__ b1g,
               const float* __restrict__ g1g, const float* __restrict__ be1g,
               const float* __restrict__ W2g, const float* __restrict__ b2g,
               const float* __restrict__ g2g, const float* __restrict__ be2g)
{
    extern __shared__ float sm[];
    float* W0s  = sm;            // 1024
    float* W1s  = sm + 1024;     // 4096
    float* W2s  = sm + 5120;     // 16384
    float* g0s  = sm + 21504;  float* be0s = sm + 21536;
    float* g1s  = sm + 21568;  float* be1s = sm + 21632;
    float* g2s  = sm + 21696;  float* be2s = sm + 21824;
    float* b0s  = sm + 21952;  float* b1s  = sm + 21984;
    float* b2s  = sm + 22048;  // weights end at 22176

    const int tid  = threadIdx.x;
    const int hp   = tid >> 8;        // which half
    const int ltid = tid & 255;

    float* pb    = sm + 22176 + hp * 14080;
    float* bufA  = pb;           // 8704: x0 @LD36 then h1 @LD68 (128 rows)
    float* bufB  = pb + 8704;    // 4608: h0 @LD36; reused as L2 partials 16x128
    float* agg   = pb + 13312;   // 256 (2 polys)
    float* sterm = pb + 13568;   // 256 (2 polys)
    float* part  = pb + 13824;   // 256

    // stage weights once per block (block-wide)
    for (int i = tid; i < 256;  i += 512) ((float4*)W0s)[i] = ((const float4*)W0g)[i];
    for (int i = tid; i < 1024; i += 512) ((float4*)W1s)[i] = ((const float4*)W1g)[i];
    for (int i = tid; i < 4096; i += 512) ((float4*)W2s)[i] = ((const float4*)W2g)[i];
    if (tid < 32)  { g0s[tid] = g0g[tid]; be0s[tid] = be0g[tid]; b0s[tid] = b0g[tid]; }
    else if (tid < 96)  { g1s[tid-32] = g1g[tid-32]; be1s[tid-32] = be1g[tid-32]; b1s[tid-32] = b1g[tid-32]; }
    else if (tid < 224) { g2s[tid-96] = g2g[tid-96]; be2s[tid-96] = be2g[tid-96]; b2s[tid-96] = b2g[tid-96]; }
    __syncthreads();   // only block-wide sync; halves free-run after this

    // ---- initial x0 load: 2 polys = 128 rows x 32 ch, channel 31 zeroed ----
    {
        const int quad = blockIdx.x;
        const int b = quad >> 6, qi = quad & 63;
        const int poly0 = qi * 4 + hp * 2;
        const float* base = data + ((size_t)b * 16385 + 1 + (size_t)poly0 * 64) * 32;
#pragma unroll
        for (int t = 0; t < 4; t++) {
            int e4 = ltid + t * 256;
            float4 v = ((const float4*)base)[e4];
            int r = e4 >> 3, kq = e4 & 7;
            if (kq == 7) v.w = 0.f;
            *reinterpret_cast<float4*>(bufA + r * 36 + kq * 4) = v;
        }
    }
    hbar(hp);

    for (int quad = blockIdx.x; quad < NQUADS; quad += MAIN_GRID) {
        const int b = quad >> 6, qi = quad & 63;
        const int poly0 = qi * 4 + hp * 2;

        // ---- layer 0 ----  (bufA x0 LD36 -> bufB h0 LD36), sterm = b0 shared
        gemm_ln_relu<32, 32, 2, 36, 36, true, 0>(bufA, bufB, W0s, g0s, be0s, b0s, ltid);
        hbar(hp);
        colmax_part<32, 36>(bufB, part, ltid);          // 8 chunks x 32
        hbar(hp);
        if (ltid < 64) {                                 // agg0[poly*32+col]
            int poly = ltid >> 5, col = ltid & 31;
            float m = part[(poly * 4) * 32 + col];
#pragma unroll
            for (int c = 1; c < 4; c++) m = fmaxf(m, part[(poly * 4 + c) * 32 + col]);
            agg[poly * 32 + col] = m;
        }
        hbar(hp);
        if (ltid < 128) {                                // sterm1 = b1 + agg0 @ W1low
            int poly = ltid >> 6, col = ltid & 63;
            float v = b1s[col];
#pragma unroll
            for (int k = 0; k < 32; k++)
                v = fmaf(agg[poly * 32 + k], W1s[(32 + k) * 64 + col], v);
            sterm[poly * 64 + col] = v;
        }
        hbar(hp);

        // ---- layer 1 ----  (bufB h0 LD36 -> bufA h1 LD68)
        gemm_ln_relu<32, 64, 4, 36, 68, true, 64>(bufB, bufA, W1s, g1s, be1s, sterm, ltid);
        hbar(hp);
        colmax_part<64, 68>(bufA, part, ltid);          // 4 chunks x 64
        hbar(hp);
        if (ltid < 128) {                                // agg1[poly*64+col]
            int poly = ltid >> 6, col = ltid & 63;
            agg[poly * 64 + col] =
                fmaxf(part[(poly * 2) * 64 + col], part[(poly * 2 + 1) * 64 + col]);
        }
        hbar(hp);
        {                                                // sterm2 = b2 + agg1 @ W2low
            int poly = ltid >> 7, col = ltid & 127;
            float v = b2s[col];
#pragma unroll
            for (int k = 0; k < 64; k++)
                v = fmaf(agg[poly * 64 + k], W2s[(64 + k) * 128 + col], v);
            sterm[ltid] = v;
        }
        hbar(hp);

        // ---- layer 2 ----  (bufA h1 LD68 -> bufB rowgroup max partials 16x128)
        gemm_ln_relu<64, 128, 8, 68, 128, false, 128>(bufA, bufB, W2s, g2s, be2s, sterm, ltid);
        hbar(hp);

        // ---- final phase: next x0 LDG issue, agg2 reduce+store, x0 STS ----
        int nq = quad + MAIN_GRID;
        if (nq >= NQUADS) nq = quad;                    // harmless reload on last
        const int nb = nq >> 6, nqi = nq & 63;
        const int npoly0 = nqi * 4 + hp * 2;
        const float* nbase = data + ((size_t)nb * 16385 + 1 + (size_t)npoly0 * 64) * 32;
        float4 xp[4];
#pragma unroll
        for (int t = 0; t < 4; t++) xp[t] = ((const float4*)nbase)[ltid + t * 256];

        {   // agg2 over 8 rowgroups per poly -> g_agg
            int poly = ltid >> 7, col = ltid & 127;
            float m = bufB[(poly * 8) * 128 + col];
#pragma unroll
            for (int r = 1; r < 8; r++) m = fmaxf(m, bufB[(poly * 8 + r) * 128 + col]);
            g_agg[((size_t)(b * 256 + poly0 + poly)) * 128 + col] = m;
        }

#pragma unroll
        for (int t = 0; t < 4; t++) {
            int e4 = ltid + t * 256;
            int r = e4 >> 3, kq = e4 & 7;
            if (kq == 7) xp[t].w = 0.f;
            *reinterpret_cast<float4*>(bufA + r * 36 + kq * 4) = xp[t];
        }
        hbar(hp);
    }
}

// ---------------------------------------------------------------------------
// Attention kernel: one block per batch, 512 threads, split partials.
// q = P[agent]@Wq'+bq; t = Wk'q; scores = P@t/16; softmax; out = (att@P)@Wv'+bv
// (Wx' = Wx[:128]+Wx[128:] since P halves are identical; bk drops in softmax)
// ---------------------------------------------------------------------------
__global__ void __launch_bounds__(512, 1)
vn_attn_kernel(const float* __restrict__ data,
               const float* __restrict__ Wq, const float* __restrict__ bq,
               const float* __restrict__ Wk,
               const float* __restrict__ Wv, const float* __restrict__ bv,
               float* __restrict__ out)
{
    extern __shared__ float sm[];
    float* Pb   = sm;            // 256*132 = 33792
    float* q    = Pb + 33792;    // 256
    float* t    = q + 256;       // 128
    float* sc   = t + 128;       // 256
    float* w128 = sc + 256;      // 128
    float* red  = w128 + 128;    // 32
    float* part = red + 32;      // 512

    const int tid = threadIdx.x, lane = tid & 31, w = tid >> 5;
    const int b = blockIdx.x;

    const float* P = g_agg + (size_t)b * 256 * 128;
    for (int e4 = tid; e4 < 8192; e4 += 512) {
        int p = e4 >> 5, j4 = e4 & 31;
        *reinterpret_cast<float4*>(Pb + p * 132 + j4 * 4) = ((const float4*)P)[e4];
    }
    if (tid == 0) red[0] = data[(size_t)b * 16385 * 32];  // agent id
    __syncthreads();
    const int aid = (int)red[0];

    // q = P[agent] @ Wq' + bq  (k-split 2-way)
    {
        const int col = tid & 255, half = tid >> 8;
        const float* pr = Pb + aid * 132;
        float s = 0.f;
        for (int j = half * 64; j < half * 64 + 64; j++)
            s = fmaf(pr[j], Wq[j * 256 + col] + Wq[(j + 128) * 256 + col], s);
        part[half * 256 + col] = s;
    }
    __syncthreads();
    if (tid < 256) q[tid] = bq[tid] + part[tid] + part[256 + tid];
    __syncthreads();

    // t = Wk' @ q  (16 warps x 8 rows)
    for (int jj = 0; jj < 8; jj++) {
        int j = w * 8 + jj;
        float a = 0.f;
#pragma unroll
        for (int m = 0; m < 8; m++) {
            int c = lane + m * 32;
            a = fmaf(Wk[j * 256 + c] + Wk[(j + 128) * 256 + c], q[c], a);
        }
#pragma unroll
        for (int o = 16; o > 0; o >>= 1) a += __shfl_xor_sync(0xffffffffu, a, o);
        if (lane == 0) t[j] = a;
    }
    __syncthreads();

    // scores[p] = (P[p].t)/16  (16 warps x 16 rows)
    for (int pp = 0; pp < 16; pp++) {
        int p = w * 16 + pp;
        float a = 0.f;
#pragma unroll
        for (int m = 0; m < 4; m++) {
            int j = lane + m * 32;
            a = fmaf(Pb[p * 132 + j], t[j], a);
        }
#pragma unroll
        for (int o = 16; o > 0; o >>= 1) a += __shfl_xor_sync(0xffffffffu, a, o);
        if (lane == 0) sc[p] = a * 0.0625f;
    }
    __syncthreads();

    // softmax over 256 (threads 0..255)
    float v = 0.f, e = 0.f;
    if (tid < 256) {
        v = sc[tid];
        float mx = v;
#pragma unroll
        for (int o = 16; o > 0; o >>= 1) mx = fmaxf(mx, __shfl_xor_sync(0xffffffffu, mx, o));
        if (lane == 0) red[w] = mx;
    }
    __syncthreads();
    if (tid == 0) {
        float M = red[0];
        for (int i = 1; i < 8; i++) M = fmaxf(M, red[i]);
        red[8] = M;
    }
    __syncthreads();
    if (tid < 256) {
        e = __expf(v - red[8]);
        float se = e;
#pragma unroll
        for (int o = 16; o > 0; o >>= 1) se += __shfl_xor_sync(0xffffffffu, se, o);
        if (lane == 0) red[16 + w] = se;
    }
    __syncthreads();
    if (tid == 0) {
        float S = 0.f;
        for (int i = 0; i < 8; i++) S += red[16 + i];
        red[24] = 1.f / S;
    }
    __syncthreads();
    if (tid < 256) sc[tid] = e * red[24];
    __syncthreads();

    // w128 = att @ P  (4-way row split)
    {
        const int col = tid & 127, seg = tid >> 7;
        float a = 0.f;
        for (int p = seg * 64; p < seg * 64 + 64; p++)
            a = fmaf(sc[p], Pb[p * 132 + col], a);
        part[seg * 128 + col] = a;
    }
    __syncthreads();
    if (tid < 128)
        w128[tid] = part[tid] + part[128 + tid] + part[256 + tid] + part[384 + tid];
    __syncthreads();

    // out = w128 @ Wv' + bv  (k-split 2-way)
    {
        const int col = tid & 255, half = tid >> 8;
        float o = 0.f;
        for (int j = half * 64; j < half * 64 + 64; j++)
            o = fmaf(w128[j], Wv[j * 256 + col] + Wv[(j + 128) * 256 + col], o);
        part[half * 256 + col] = o;
    }
    __syncthreads();
    if (tid < 256) out[b * 256 + tid] = bv[tid] + part[tid] + part[256 + tid];
}

// ---------------------------------------------------------------------------
extern "C" void kernel_launch(void* const* d_in, const int* in_sizes, int n_in,
                              void* d_out, int out_size)
{
    const float* data = (const float*)d_in[0];
    const float* W0  = (const float*)d_in[1];
    const float* b0  = (const float*)d_in[2];
    const float* g0  = (const float*)d_in[3];
    const float* be0 = (const float*)d_in[4];
    const float* W1  = (const float*)d_in[5];
    const float* b1  = (const float*)d_in[6];
    const float* g1  = (const float*)d_in[7];
    const float* be1 = (const float*)d_in[8];
    const float* W2  = (const float*)d_in[9];
    const float* b2  = (const float*)d_in[10];
    const float* g2  = (const float*)d_in[11];
    const float* be2 = (const float*)d_in[12];
    const float* Wq  = (const float*)d_in[13];
    const float* bq  = (const float*)d_in[14];
    const float* Wk  = (const float*)d_in[15];
    // d_in[16] = bk: softmax-invariant, unused
    const float* Wv  = (const float*)d_in[17];
    const float* bv  = (const float*)d_in[18];
    float* out = (float*)d_out;

    const size_t smA = (size_t)(22176 + 2 * 14080) * sizeof(float);  // ~196.6 KB
    const size_t smB = (size_t)(33792 + 256 + 128 + 256 + 128 + 32 + 512) * sizeof(float);
    cudaFuncSetAttribute(vn_main_kernel, cudaFuncAttributeMaxDynamicSharedMemorySize, (int)smA);
    cudaFuncSetAttribute(vn_attn_kernel, cudaFuncAttributeMaxDynamicSharedMemorySize, (int)smB);

    vn_main_kernel<<<MAIN_GRID, 512, smA>>>(data, W0, b0, g0, be0,
                                            W1, b1, g1, be1, W2, b2, g2, be2);
    vn_attn_kernel<<<NB, 512, smB>>>(data, Wq, bq, Wk, Wv, bv, out);
}